// round 1
// baseline (speedup 1.0000x reference)
#include <cuda_runtime.h>

#define FULLMASK 0xffffffffu

// ---------- packed f32x2 helpers (Blackwell sm_103a) ----------
__device__ __forceinline__ unsigned long long pk2(float a, float b) {
    unsigned long long r;
    asm("mov.b64 %0, {%1, %2};" : "=l"(r) : "f"(a), "f"(b));
    return r;
}
__device__ __forceinline__ float2 upk2(unsigned long long v) {
    float2 r;
    asm("mov.b64 {%0, %1}, %2;" : "=f"(r.x), "=f"(r.y) : "l"(v));
    return r;
}
__device__ __forceinline__ unsigned long long dup2(float a) { return pk2(a, a); }

__device__ __forceinline__ unsigned long long ffma2(unsigned long long a,
                                                    unsigned long long b,
                                                    unsigned long long c) {
    unsigned long long d;
    asm("fma.rn.f32x2 %0, %1, %2, %3;" : "=l"(d) : "l"(a), "l"(b), "l"(c));
    return d;
}

// tanh(x) = 1 - 2/(exp(2x)+1) via MUFU.EX2 + MUFU.RCP (abs err ~1e-7)
__device__ __forceinline__ float tanh_fast(float xx) {
    float e;
    asm("ex2.approx.f32 %0, %1;" : "=f"(e) : "f"(xx * 2.8853900817779268f));
    float r;
    asm("rcp.approx.f32 %0, %1;" : "=f"(r) : "f"(e + 1.0f));
    return fmaf(-2.0f, r, 1.0f);
}

// Warp layout: 4 batch elements / warp; 8 lanes per element (group g = lane>>3);
// each lane owns 8 hidden units j = 8*(lane&7) .. +7.
// W2 in SMEM regrouped per lane-slot q with stride 516 floats (2064 B == 16 mod 128)
// so the 8 lanes' LDS.128 land on 8 distinct 16B bank groups -> conflict-free,
// and the 4 element-groups broadcast the same addresses.
__global__ void __launch_bounds__(32)
maxwell_ffnn_kernel(const float* __restrict__ x,
                    const float* __restrict__ W1,
                    const float* __restrict__ b1,
                    const float* __restrict__ W2,
                    const float* __restrict__ b2,
                    const float* __restrict__ W3,
                    const float* __restrict__ b3,
                    float* __restrict__ out) {
    __shared__ __align__(16) float W2s[8][516];

    const int lane = threadIdx.x & 31;

    // Stage W2: W2s[q][i*8 + u] = W2[i][8q+u]
    for (int idx = lane; idx < 4096; idx += 32) {
        int i = idx >> 6;
        int j = idx & 63;
        W2s[j >> 3][i * 8 + (j & 7)] = W2[idx];
    }
    __syncwarp();

    const int q   = lane & 7;
    const int grp = lane & 24;
    const int e   = blockIdx.x * 4 + (lane >> 3);   // element index, < 2048
    const float* w2q = &W2s[q][0];

    // Per-lane constants for owned units jb..jb+7
    const int jb = q * 8;
    unsigned long long c1a[4], c1b[4], cb1[4], cb2[4];
    float w3c[8];
#pragma unroll
    for (int k = 0; k < 4; ++k) {
        c1a[k] = pk2(__ldg(&W1[jb + 2 * k]),      __ldg(&W1[jb + 2 * k + 1]));
        c1b[k] = pk2(__ldg(&W1[64 + jb + 2 * k]), __ldg(&W1[64 + jb + 2 * k + 1]));
        cb1[k] = pk2(__ldg(&b1[jb + 2 * k]),      __ldg(&b1[jb + 2 * k + 1]));
        cb2[k] = pk2(__ldg(&b2[jb + 2 * k]),      __ldg(&b2[jb + 2 * k + 1]));
    }
#pragma unroll
    for (int u = 0; u < 8; ++u) w3c[u] = __ldg(&W3[jb + u]);
    const float b3v = __ldg(&b3[0]);

    const float2* xp = (const float2*)(x + (size_t)e * 2048);
    float* op = out + (size_t)e * 1024;

    float gamma = 0.0f;
    float2 xv = __ldg(&xp[0]);

#pragma unroll 1
    for (int t = 0; t < 1024; ++t) {
        const float eps = xv.x;
        const float dtn = xv.y;
        if (t < 1023) xv = __ldg(&xp[t + 1]);   // prefetch next step

        // h1 = tanh(eps*W1[0,:] + gamma*W1[1,:] + b1) for owned 8 units
        const unsigned long long epsd = dup2(eps);
        const unsigned long long gamd = dup2(gamma);
        float2 h[4];
#pragma unroll
        for (int k = 0; k < 4; ++k) {
            unsigned long long pre = ffma2(epsd, c1a[k], ffma2(gamd, c1b[k], cb1[k]));
            float2 p = upk2(pre);
            h[k].x = tanh_fast(p.x);
            h[k].y = tanh_fast(p.y);
        }

        // acc[c] = b2 slice; accumulate h1 @ W2 for owned 8 outputs
        unsigned long long acc0 = cb2[0], acc1 = cb2[1], acc2 = cb2[2], acc3 = cb2[3];
#pragma unroll
        for (int ks = 0; ks < 4; ++ks) {
            const float hsx = h[ks].x;
            const float hsy = h[ks].y;
#pragma unroll
            for (int qs = 0; qs < 8; ++qs) {
                // h1[i0], h1[i0+1] where i0 = 8*qs + 2*ks (owned by lane grp+qs)
                float v0 = __shfl_sync(FULLMASK, hsx, grp + qs);
                float v1 = __shfl_sync(FULLMASK, hsy, grp + qs);
                unsigned long long v0d = dup2(v0);
                unsigned long long v1d = dup2(v1);
                const ulonglong2* rp =
                    (const ulonglong2*)(w2q + (qs * 8 + ks * 2) * 8);
                ulonglong2 wa = rp[0], wb = rp[1];   // row i0   (8 floats)
                ulonglong2 wc = rp[2], wd = rp[3];   // row i0+1 (8 floats)
                acc0 = ffma2(v0d, wa.x, acc0);
                acc1 = ffma2(v0d, wa.y, acc1);
                acc2 = ffma2(v0d, wb.x, acc2);
                acc3 = ffma2(v0d, wb.y, acc3);
                acc0 = ffma2(v1d, wc.x, acc0);
                acc1 = ffma2(v1d, wc.y, acc1);
                acc2 = ffma2(v1d, wd.x, acc2);
                acc3 = ffma2(v1d, wd.y, acc3);
            }
        }

        // h2 = tanh(acc); partial W3 dot over owned units
        float gp = 0.0f;
        {
            float2 a0 = upk2(acc0), a1 = upk2(acc1), a2 = upk2(acc2), a3 = upk2(acc3);
            gp = fmaf(tanh_fast(a0.x), w3c[0], gp);
            gp = fmaf(tanh_fast(a0.y), w3c[1], gp);
            gp = fmaf(tanh_fast(a1.x), w3c[2], gp);
            gp = fmaf(tanh_fast(a1.y), w3c[3], gp);
            gp = fmaf(tanh_fast(a2.x), w3c[4], gp);
            gp = fmaf(tanh_fast(a2.y), w3c[5], gp);
            gp = fmaf(tanh_fast(a3.x), w3c[6], gp);
            gp = fmaf(tanh_fast(a3.y), w3c[7], gp);
        }

        // reduce across the 8 lanes of this element's group (stays in group)
        gp += __shfl_xor_sync(FULLMASK, gp, 1);
        gp += __shfl_xor_sync(FULLMASK, gp, 2);
        gp += __shfl_xor_sync(FULLMASK, gp, 4);

        const float gdot = gp + b3v;
        gamma = fmaf(dtn, gdot, gamma);

        // sigma = 0.5*eps + 2*(eps - gamma) = 2.5*eps - 2*gamma
        if (q == 0) op[t] = fmaf(-2.0f, gamma, 2.5f * eps);
    }
}

extern "C" void kernel_launch(void* const* d_in, const int* in_sizes, int n_in,
                              void* d_out, int out_size) {
    (void)in_sizes; (void)n_in; (void)out_size;
    const float* x  = (const float*)d_in[0];
    const float* W1 = (const float*)d_in[1];
    const float* b1 = (const float*)d_in[2];
    const float* W2 = (const float*)d_in[3];
    const float* b2 = (const float*)d_in[4];
    const float* W3 = (const float*)d_in[5];
    const float* b3 = (const float*)d_in[6];
    float* out = (float*)d_out;

    // 2048 elements / 4 per warp = 512 single-warp CTAs (~3.5/SM)
    maxwell_ffnn_kernel<<<512, 32>>>(x, W1, b1, W2, b2, W3, b3, out);
}

// round 2
// speedup vs baseline: 1.1815x; 1.1815x over previous
#include <cuda_runtime.h>

#define FULLMASK 0xffffffffu

// ---------- packed f32x2 helpers (Blackwell sm_103a) ----------
__device__ __forceinline__ unsigned long long pk2(float a, float b) {
    unsigned long long r;
    asm("mov.b64 %0, {%1, %2};" : "=l"(r) : "f"(a), "f"(b));
    return r;
}
__device__ __forceinline__ float2 upk2(unsigned long long v) {
    float2 r;
    asm("mov.b64 {%0, %1}, %2;" : "=f"(r.x), "=f"(r.y) : "l"(v));
    return r;
}
__device__ __forceinline__ unsigned long long dup2(float a) { return pk2(a, a); }

__device__ __forceinline__ unsigned long long ffma2(unsigned long long a,
                                                    unsigned long long b,
                                                    unsigned long long c) {
    unsigned long long d;
    asm("fma.rn.f32x2 %0, %1, %2, %3;" : "=l"(d) : "l"(a), "l"(b), "l"(c));
    return d;
}

// tanh(x) = 1 - 2/(exp(2x)+1) via MUFU.EX2 + MUFU.RCP (abs err ~1e-7)
__device__ __forceinline__ float tanh_fast(float xx) {
    float e;
    asm("ex2.approx.f32 %0, %1;" : "=f"(e) : "f"(xx * 2.8853900817779268f));
    float r;
    asm("rcp.approx.f32 %0, %1;" : "=f"(r) : "f"(e + 1.0f));
    return fmaf(-2.0f, r, 1.0f);
}

// One warp per batch element. Lane l:
//   - computes h1 units (2l, 2l+1)           [2 ffma2 + 2 tanh]
//   - publishes the pair via SMEM (STS.64), reads all 32 pairs back with
//     16 broadcast LDS.128 (all lanes same address -> conflict-free N=1)
//   - owns output columns l and l+32 of layer 2; W2 lives in 128 registers
//     as row-paired f32x2 -> 64 ffma2, no dup MOVs
//   - shfl_xor butterfly gives every lane the identical gamma_dot sum.
__global__ void __launch_bounds__(32)
maxwell_ffnn_kernel(const float* __restrict__ x,
                    const float* __restrict__ W1,
                    const float* __restrict__ b1,
                    const float* __restrict__ W2,
                    const float* __restrict__ b2,
                    const float* __restrict__ W3,
                    const float* __restrict__ b3,
                    float* __restrict__ out) {
    __shared__ __align__(16) unsigned long long hbuf[2][32];

    const int l = threadIdx.x & 31;
    const int e = blockIdx.x;            // element index, < 2048
    const int jA = l;                    // owned output col A
    const int jB = l + 32;               // owned output col B
    const int u0 = 2 * l;                // owned h1 units u0, u0+1

    // ---- loop-invariant weights into registers ----
    // Layer 1 constants for units (u0, u0+1), packed.
    const unsigned long long c1a = pk2(__ldg(&W1[u0]),      __ldg(&W1[u0 + 1]));
    const unsigned long long c1b = pk2(__ldg(&W1[64 + u0]), __ldg(&W1[64 + u0 + 1]));
    const unsigned long long cb1 = pk2(__ldg(&b1[u0]),      __ldg(&b1[u0 + 1]));

    // W2 columns jA, jB packed by row pairs: w2A[s] = (W2[2s][jA], W2[2s+1][jA])
    unsigned long long w2A[32], w2B[32];
#pragma unroll
    for (int s = 0; s < 32; ++s) {
        w2A[s] = pk2(__ldg(&W2[(2 * s) * 64 + jA]), __ldg(&W2[(2 * s + 1) * 64 + jA]));
        w2B[s] = pk2(__ldg(&W2[(2 * s) * 64 + jB]), __ldg(&W2[(2 * s + 1) * 64 + jB]));
    }
    const float b2A = __ldg(&b2[jA]);
    const float b2B = __ldg(&b2[jB]);
    const float w3A = __ldg(&W3[jA]);
    const float w3B = __ldg(&W3[jB]);
    const float b3v = __ldg(&b3[0]);

    const float2* xp = (const float2*)(x + (size_t)e * 2048);
    float* op = out + (size_t)e * 1024;

    float gamma = 0.0f;
    float2 xv = __ldg(&xp[0]);

#pragma unroll 1
    for (int t = 0; t < 1024; ++t) {
        const float eps = xv.x;
        const float dtn = xv.y;
        if (t < 1023) xv = __ldg(&xp[t + 1]);   // prefetch next step (broadcast LDG)

        // ---- layer 1: my 2 units ----
        unsigned long long pre =
            ffma2(dup2(eps), c1a, ffma2(dup2(gamma), c1b, cb1));
        float2 p = upk2(pre);
        const unsigned long long hpair = pk2(tanh_fast(p.x), tanh_fast(p.y));

        // ---- publish h pair, read all 32 pairs (broadcast LDS.128) ----
        const int buf = t & 1;
        hbuf[buf][l] = hpair;
        __syncwarp();
        const ulonglong2* hp = (const ulonglong2*)&hbuf[buf][0];

        // ---- layer 2: 64 ffma2, paired-row accumulators ----
        unsigned long long accA = pk2(b2A, 0.0f);
        unsigned long long accB = pk2(b2B, 0.0f);
#pragma unroll
        for (int k = 0; k < 16; ++k) {
            const ulonglong2 hh = hp[k];
            accA = ffma2(hh.x, w2A[2 * k],     accA);
            accB = ffma2(hh.x, w2B[2 * k],     accB);
            accA = ffma2(hh.y, w2A[2 * k + 1], accA);
            accB = ffma2(hh.y, w2B[2 * k + 1], accB);
        }
        const float2 aA = upk2(accA);
        const float2 aB = upk2(accB);
        const float h2A = tanh_fast(aA.x + aA.y);
        const float h2B = tanh_fast(aB.x + aB.y);

        // ---- layer 3 partial + full butterfly reduce (identical on all lanes) ----
        float gp = fmaf(h2A, w3A, h2B * w3B);
        gp += __shfl_xor_sync(FULLMASK, gp, 1);
        gp += __shfl_xor_sync(FULLMASK, gp, 2);
        gp += __shfl_xor_sync(FULLMASK, gp, 4);
        gp += __shfl_xor_sync(FULLMASK, gp, 8);
        gp += __shfl_xor_sync(FULLMASK, gp, 16);

        gamma = fmaf(dtn, gp + b3v, gamma);

        // sigma = 0.5*eps + 2*(eps - gamma) = 2.5*eps - 2*gamma
        if (l == 0) op[t] = fmaf(-2.0f, gamma, 2.5f * eps);
    }
}

extern "C" void kernel_launch(void* const* d_in, const int* in_sizes, int n_in,
                              void* d_out, int out_size) {
    (void)in_sizes; (void)n_in; (void)out_size;
    const float* x  = (const float*)d_in[0];
    const float* W1 = (const float*)d_in[1];
    const float* b1 = (const float*)d_in[2];
    const float* W2 = (const float*)d_in[3];
    const float* b2 = (const float*)d_in[4];
    const float* W3 = (const float*)d_in[5];
    const float* b3 = (const float*)d_in[6];
    float* out = (float*)d_out;

    // one warp per element: 2048 single-warp CTAs (~12/SM, RF-limited)
    maxwell_ffnn_kernel<<<2048, 32>>>(x, W1, b1, W2, b2, W3, b3, out);
}

// round 4
// speedup vs baseline: 1.7168x; 1.4531x over previous
#include <cuda_runtime.h>

#define FULLMASK 0xffffffffu

// ---------- packed f32x2 helpers (Blackwell sm_103a) ----------
__device__ __forceinline__ unsigned long long pk2(float a, float b) {
    unsigned long long r;
    asm("mov.b64 %0, {%1, %2};" : "=l"(r) : "f"(a), "f"(b));
    return r;
}
__device__ __forceinline__ float2 upk2(unsigned long long v) {
    float2 r;
    asm("mov.b64 {%0, %1}, %2;" : "=f"(r.x), "=f"(r.y) : "l"(v));
    return r;
}
__device__ __forceinline__ unsigned long long dup2(float a) { return pk2(a, a); }

__device__ __forceinline__ unsigned long long ffma2(unsigned long long a,
                                                    unsigned long long b,
                                                    unsigned long long c) {
    unsigned long long d;
    asm("fma.rn.f32x2 %0, %1, %2, %3;" : "=l"(d) : "l"(a), "l"(b), "l"(c));
    return d;
}
__device__ __forceinline__ unsigned long long add2(unsigned long long a,
                                                   unsigned long long b) {
    unsigned long long d;
    asm("add.rn.f32x2 %0, %1, %2;" : "=l"(d) : "l"(a), "l"(b));
    return d;
}

// tanh(x) = 1 - 2/(exp(2x)+1) via MUFU.EX2 + MUFU.RCP (abs err ~1e-7)
__device__ __forceinline__ float tanh_fast(float xx) {
    float e;
    asm("ex2.approx.f32 %0, %1;" : "=f"(e) : "f"(xx * 2.8853900817779268f));
    float r;
    asm("rcp.approx.f32 %0, %1;" : "=f"(r) : "f"(e + 1.0f));
    return fmaf(-2.0f, r, 1.0f);
}

// TWO batch elements per warp (independent recurrences -> 2x ILP, shared weights).
// Lane l: computes h1 units (2l,2l+1) for both elements, publishes via SMEM,
// owns layer-2 output columns l and l+32 (W2 in 128 regs as row-paired f32x2).
// Warp sums: two interleaved 5-round shfl_xor butterflies (latencies overlap).
__global__ void __launch_bounds__(32)
maxwell_ffnn_kernel(const float* __restrict__ x,
                    const float* __restrict__ W1,
                    const float* __restrict__ b1,
                    const float* __restrict__ W2,
                    const float* __restrict__ b2,
                    const float* __restrict__ W3,
                    const float* __restrict__ b3,
                    float* __restrict__ out) {
    __shared__ __align__(16) unsigned long long hbuf[2][2][32];  // [buf][elem][lane]

    const int l  = threadIdx.x & 31;
    const int jA = l;
    const int jB = l + 32;
    const int u0 = 2 * l;

    // ---- loop-invariant weights in registers ----
    const unsigned long long c1a = pk2(__ldg(&W1[u0]),      __ldg(&W1[u0 + 1]));
    const unsigned long long c1b = pk2(__ldg(&W1[64 + u0]), __ldg(&W1[64 + u0 + 1]));
    const unsigned long long cb1 = pk2(__ldg(&b1[u0]),      __ldg(&b1[u0 + 1]));

    unsigned long long w2A[32], w2B[32];
#pragma unroll
    for (int s = 0; s < 32; ++s) {
        w2A[s] = pk2(__ldg(&W2[(2 * s) * 64 + jA]), __ldg(&W2[(2 * s + 1) * 64 + jA]));
        w2B[s] = pk2(__ldg(&W2[(2 * s) * 64 + jB]), __ldg(&W2[(2 * s + 1) * 64 + jB]));
    }
    const float b2A = __ldg(&b2[jA]);
    const float b2B = __ldg(&b2[jB]);
    const float w3A = __ldg(&W3[jA]);
    const float w3B = __ldg(&W3[jB]);
    const float b3v = __ldg(&b3[0]);

    const float2* xp[2];
    float*        op[2];
#pragma unroll
    for (int e = 0; e < 2; ++e) {
        const int elem = blockIdx.x * 2 + e;
        xp[e] = (const float2*)(x + (size_t)elem * 2048);
        op[e] = out + (size_t)elem * 1024;
    }

    float  gamma[2] = {0.0f, 0.0f};
    float2 xv[2]    = {__ldg(&xp[0][0]), __ldg(&xp[1][0])};
    const unsigned long long zero2 = pk2(0.0f, 0.0f);

#pragma unroll 1
    for (int t = 0; t < 1024; ++t) {
        float eps[2], dtn[2];
#pragma unroll
        for (int e = 0; e < 2; ++e) {
            eps[e] = xv[e].x;
            dtn[e] = xv[e].y;
            if (t < 1023) xv[e] = __ldg(&xp[e][t + 1]);   // prefetch
        }

        // ---- layer 1 (both elements) ----
        const int buf = t & 1;
#pragma unroll
        for (int e = 0; e < 2; ++e) {
            unsigned long long pre =
                ffma2(dup2(gamma[e]), c1b, ffma2(dup2(eps[e]), c1a, cb1));
            float2 p = upk2(pre);
            hbuf[buf][e][l] = pk2(tanh_fast(p.x), tanh_fast(p.y));
        }
        __syncwarp();

        // ---- layer 2 + 3 (both elements) ----
        float gp[2];
#pragma unroll
        for (int e = 0; e < 2; ++e) {
            const ulonglong2* hp = (const ulonglong2*)&hbuf[buf][e][0];
            // split accumulator chains: depth 16 each
            unsigned long long A0 = pk2(b2A, 0.0f), A1 = zero2;
            unsigned long long B0 = pk2(b2B, 0.0f), B1 = zero2;
#pragma unroll
            for (int k = 0; k < 16; ++k) {
                const ulonglong2 hh = hp[k];
                A0 = ffma2(hh.x, w2A[2 * k],     A0);
                B0 = ffma2(hh.x, w2B[2 * k],     B0);
                A1 = ffma2(hh.y, w2A[2 * k + 1], A1);
                B1 = ffma2(hh.y, w2B[2 * k + 1], B1);
            }
            const float2 aA = upk2(add2(A0, A1));
            const float2 aB = upk2(add2(B0, B1));
            const float h2A = tanh_fast(aA.x + aA.y);
            const float h2B = tanh_fast(aB.x + aB.y);
            gp[e] = fmaf(h2A, w3A, h2B * w3B);
        }

        // ---- warp-wide sums: interleaved butterflies (latencies overlap) ----
#pragma unroll
        for (int d = 1; d < 32; d <<= 1) {
            const float s0 = __shfl_xor_sync(FULLMASK, gp[0], d);
            const float s1 = __shfl_xor_sync(FULLMASK, gp[1], d);
            gp[0] += s0;
            gp[1] += s1;
        }

        // ---- gamma update + output ----
#pragma unroll
        for (int e = 0; e < 2; ++e) {
            gamma[e] = fmaf(dtn[e], gp[e] + b3v, gamma[e]);
            // sigma = 0.5*eps + 2*(eps - gamma) = 2.5*eps - 2*gamma
            if (l == e) op[e][t] = fmaf(-2.0f, gamma[e], 2.5f * eps[e]);
        }
    }
}

extern "C" void kernel_launch(void* const* d_in, const int* in_sizes, int n_in,
                              void* d_out, int out_size) {
    (void)in_sizes; (void)n_in; (void)out_size;
    const float* x  = (const float*)d_in[0];
    const float* W1 = (const float*)d_in[1];
    const float* b1 = (const float*)d_in[2];
    const float* W2 = (const float*)d_in[3];
    const float* b2 = (const float*)d_in[4];
    const float* W3 = (const float*)d_in[5];
    const float* b3 = (const float*)d_in[6];
    float* out = (float*)d_out;

    // 2 elements per warp: 1024 single-warp CTAs (~7/SM, single wave)
    maxwell_ffnn_kernel<<<1024, 32>>>(x, W1, b1, W2, b2, W3, b3, out);
}